// round 1
// baseline (speedup 1.0000x reference)
#include <cuda_runtime.h>

// DIN fused kernel set for sm_103a.
// K0: V = candidate @ W_c + fc1_b           (fp32)
// K1: persistent fused attention per batch  (tf32 mma.sync, fp32 accum)
// K2: MLP  logit = relu(x@mlp1+b)@mlp2 + b2 (fp32)

#define S_LEN 200
#define E_DIM 128
#define XPAD  132   // 132 mod 32 == 4 -> conflict-free A-fragment loads

__device__ float g_V[4096 * 128];   // per-batch candidate projection
__device__ float g_x[4096 * 256];   // concat(user_interest, candidate)

__device__ __forceinline__ float tf32r(float x) {
    unsigned u;
    asm("cvt.rna.tf32.f32 %0, %1;" : "=r"(u) : "f"(x));
    return __uint_as_float(u);
}

__device__ __forceinline__ void mma8(float* d, const float* a, const float* b) {
    asm volatile(
        "mma.sync.aligned.m16n8k8.row.col.f32.tf32.tf32.f32 "
        "{%0,%1,%2,%3}, {%4,%5,%6,%7}, {%8,%9}, {%0,%1,%2,%3};"
        : "+f"(d[0]), "+f"(d[1]), "+f"(d[2]), "+f"(d[3])
        : "r"(__float_as_uint(a[0])), "r"(__float_as_uint(a[1])),
          "r"(__float_as_uint(a[2])), "r"(__float_as_uint(a[3])),
          "r"(__float_as_uint(b[0])), "r"(__float_as_uint(b[1])));
}

// ---------------------------------------------------------------------------
// K0: g_V[b][j] = sum_k cand[b][k] * fc1_w[128+k][j] + fc1_b[j]
// grid = nb/64, 256 threads, dyn smem 96KB
// ---------------------------------------------------------------------------
__global__ __launch_bounds__(256) void din_cand_kernel(
    const float* __restrict__ cand, const float* __restrict__ fc1w,
    const float* __restrict__ fc1b, int nb)
{
    extern __shared__ float s0[];
    float* cs = s0;           // 64 x 128
    float* ws = s0 + 8192;    // 128 x 128
    const int tid = threadIdx.x;
    const int rowbase = blockIdx.x * 64;

    const float4* c4 = (const float4*)(cand + (size_t)rowbase * 128);
#pragma unroll
    for (int i = 0; i < 8; i++) ((float4*)cs)[tid + i * 256] = c4[tid + i * 256];
    const float4* w4 = (const float4*)(fc1w + 128 * 128);
#pragma unroll
    for (int i = 0; i < 16; i++) ((float4*)ws)[tid + i * 256] = w4[tid + i * 256];
    __syncthreads();

    const int ty = tid >> 4, tx = tid & 15;
    float acc[4][8];
#pragma unroll
    for (int i = 0; i < 4; i++)
#pragma unroll
        for (int j = 0; j < 8; j++) acc[i][j] = 0.f;

    for (int k = 0; k < 128; k++) {
        float ra[4];
#pragma unroll
        for (int i = 0; i < 4; i++) ra[i] = cs[(ty * 4 + i) * 128 + k];
        float4 b0 = *(const float4*)(ws + k * 128 + tx * 8);
        float4 b1 = *(const float4*)(ws + k * 128 + tx * 8 + 4);
        float rb[8] = {b0.x, b0.y, b0.z, b0.w, b1.x, b1.y, b1.z, b1.w};
#pragma unroll
        for (int i = 0; i < 4; i++)
#pragma unroll
            for (int j = 0; j < 8; j++) acc[i][j] += ra[i] * rb[j];
    }
#pragma unroll
    for (int i = 0; i < 4; i++)
#pragma unroll
        for (int j = 0; j < 8; j++)
            g_V[(size_t)(rowbase + ty * 4 + i) * 128 + tx * 8 + j] =
                acc[i][j] + fc1b[tx * 8 + j];
}

// ---------------------------------------------------------------------------
// K1: persistent fused attention.
// 256 threads, 8 warps; warp w owns output cols [16w,16w+16) of h.
// W_b held as tf32 mma B-fragments in registers (64/thread).
// smem: Xs 200x132 (tf32-rounded) | part[8][208] | v[128] | red[64]
// ---------------------------------------------------------------------------
#define K1_SMEM_WORDS (26400 + 8 * 208 + 128 + 64)

__global__ __launch_bounds__(256, 2) void din_attn_kernel(
    const float* __restrict__ beh, const float* __restrict__ cand,
    const float* __restrict__ fc1w, const float* __restrict__ fc2w, int nb)
{
    extern __shared__ float sm[];
    float* Xs   = sm;                 // 26400
    float* part = sm + 26400;         // 8 * 208
    float* vbuf = sm + 26400 + 1664;  // 128
    float* red  = sm + 26400 + 1664 + 128;  // 64

    const int tid = threadIdx.x;
    const int wid = tid >> 5;
    const int lane = tid & 31;
    const int g = lane >> 2;
    const int l4 = lane & 3;

    // ---- preload W_b fragments + w2 (constant across batches) ----
    float Bf[16][2][2];
#pragma unroll
    for (int kt = 0; kt < 16; kt++)
#pragma unroll
        for (int nt = 0; nt < 2; nt++) {
            int n = wid * 16 + nt * 8 + g;
            Bf[kt][nt][0] = tf32r(fc1w[(kt * 8 + l4) * 128 + n]);
            Bf[kt][nt][1] = tf32r(fc1w[(kt * 8 + 4 + l4) * 128 + n]);
        }
    float w2v[2][2];
#pragma unroll
    for (int nt = 0; nt < 2; nt++) {
        int c = wid * 16 + nt * 8 + 2 * l4;
        w2v[nt][0] = fc2w[c];
        w2v[nt][1] = fc2w[c + 1];
    }

    for (int b = blockIdx.x; b < nb; b += gridDim.x) {
        // ---- load X (tf32-round at store) ----
        const float4* src = (const float4*)(beh + (size_t)b * (S_LEN * E_DIM));
#pragma unroll
        for (int it = 0; it < 25; it++) {
            int i = tid + it * 256;
            float4 v = src[i];
            v.x = tf32r(v.x); v.y = tf32r(v.y); v.z = tf32r(v.z); v.w = tf32r(v.w);
            int r = i >> 5, c4 = i & 31;
            *(float4*)(Xs + r * XPAD + c4 * 4) = v;
        }
        if (tid < 128) vbuf[tid] = g_V[(size_t)b * 128 + tid];
        __syncthreads();

        float vv[2][2];
#pragma unroll
        for (int nt = 0; nt < 2; nt++) {
            int c = wid * 16 + nt * 8 + 2 * l4;
            vv[nt][0] = vbuf[c];
            vv[nt][1] = vbuf[c + 1];
        }

        // ---- mma: h = relu(X@W_b + v), per-row partial score = sum relu*w2 ----
        for (int mt = 0; mt < 13; mt++) {
            int m0 = mt * 16;
            int r0 = m0 + g;     if (r0 > 199) r0 = 199;   // phantom rows (discarded)
            int r1 = m0 + 8 + g; if (r1 > 199) r1 = 199;
            const float* x0 = Xs + r0 * XPAD;
            const float* x1 = Xs + r1 * XPAD;
            float acc0[4] = {0.f, 0.f, 0.f, 0.f};
            float acc1[4] = {0.f, 0.f, 0.f, 0.f};
#pragma unroll
            for (int kt = 0; kt < 16; kt++) {
                float a[4];
                a[0] = x0[kt * 8 + l4];
                a[1] = x1[kt * 8 + l4];
                a[2] = x0[kt * 8 + 4 + l4];
                a[3] = x1[kt * 8 + 4 + l4];
                mma8(acc0, a, Bf[kt][0]);
                mma8(acc1, a, Bf[kt][1]);
            }
            float p0 =
                fmaxf(acc0[0] + vv[0][0], 0.f) * w2v[0][0] +
                fmaxf(acc0[1] + vv[0][1], 0.f) * w2v[0][1] +
                fmaxf(acc1[0] + vv[1][0], 0.f) * w2v[1][0] +
                fmaxf(acc1[1] + vv[1][1], 0.f) * w2v[1][1];
            float p1 =
                fmaxf(acc0[2] + vv[0][0], 0.f) * w2v[0][0] +
                fmaxf(acc0[3] + vv[0][1], 0.f) * w2v[0][1] +
                fmaxf(acc1[2] + vv[1][0], 0.f) * w2v[1][0] +
                fmaxf(acc1[3] + vv[1][1], 0.f) * w2v[1][1];
            p0 += __shfl_xor_sync(0xffffffffu, p0, 1);
            p0 += __shfl_xor_sync(0xffffffffu, p0, 2);
            p1 += __shfl_xor_sync(0xffffffffu, p1, 1);
            p1 += __shfl_xor_sync(0xffffffffu, p1, 2);
            if (l4 == 0) {
                part[wid * 208 + m0 + g] = p0;
                part[wid * 208 + m0 + 8 + g] = p1;
            }
        }
        __syncthreads();

        // ---- scores = sum over warps (deterministic), softmax ----
        float sc = -3.4e38f;
        if (tid < S_LEN) {
            sc = 0.f;
#pragma unroll
            for (int w = 0; w < 8; w++) sc += part[w * 208 + tid];
        }
        float mx = sc;
#pragma unroll
        for (int o = 16; o; o >>= 1) mx = fmaxf(mx, __shfl_xor_sync(0xffffffffu, mx, o));
        if (lane == 0) red[wid] = mx;
        __syncthreads();
        mx = red[0];
#pragma unroll
        for (int w = 1; w < 8; w++) mx = fmaxf(mx, red[w]);
        float ex = (tid < S_LEN) ? __expf(sc - mx) : 0.f;
        float sum = ex;
#pragma unroll
        for (int o = 16; o; o >>= 1) sum += __shfl_xor_sync(0xffffffffu, sum, o);
        if (lane == 0) red[8 + wid] = sum;
        __syncthreads();
        sum = 0.f;
#pragma unroll
        for (int w = 0; w < 8; w++) sum += red[8 + w];
        if (tid < S_LEN) part[tid] = ex / sum;   // attn -> part row 0
        __syncthreads();

        // ---- user_interest = attn @ X ; write concat(ui, cand) ----
        {
            int e = tid & 127;
            int h = tid >> 7;
            float acc = 0.f;
            int s0i = h * 100;
#pragma unroll 4
            for (int s = s0i; s < s0i + 100; s++)
                acc += part[s] * Xs[s * XPAD + e];
            if (h == 1) {
                part[208 + e] = acc;                       // temp in part row 1
                g_x[(size_t)b * 256 + 128 + e] = cand[(size_t)b * 128 + e];
            }
            __syncthreads();
            if (h == 0) g_x[(size_t)b * 256 + e] = acc + part[208 + e];
        }
        __syncthreads();   // protect smem before next batch
    }
}

// ---------------------------------------------------------------------------
// K2: logit[r] = relu(x[r]@mlp1 + b1) @ mlp2 + b2
// grid = nb/16, 256 threads; warp ty owns rows {2ty, 2ty+1}, lanes own 8 cols.
// ---------------------------------------------------------------------------
__global__ __launch_bounds__(256) void din_mlp_kernel(
    const float* __restrict__ w1, const float* __restrict__ b1,
    const float* __restrict__ w2, const float* __restrict__ b2,
    float* __restrict__ out, int nb)
{
    __shared__ float xs[16 * 256];
    __shared__ float ws[16 * 256];
    const int tid = threadIdx.x, lane = tid & 31, ty = tid >> 5;
    const int rb = blockIdx.x * 16;

    const float4* x4 = (const float4*)(g_x + (size_t)rb * 256);
#pragma unroll
    for (int i = 0; i < 4; i++) ((float4*)xs)[tid + i * 256] = x4[tid + i * 256];

    float b1l[8], w2l[8];
#pragma unroll
    for (int j = 0; j < 8; j++) {
        b1l[j] = b1[lane * 8 + j];
        w2l[j] = w2[lane * 8 + j];
    }
    float acc0[8], acc1[8];
#pragma unroll
    for (int j = 0; j < 8; j++) { acc0[j] = 0.f; acc1[j] = 0.f; }
    const int r0 = ty * 2, r1 = r0 + 1;

    for (int kt = 0; kt < 16; kt++) {
        __syncthreads();   // prior-iter consumers done (also fences xs load at kt=0)
        const float4* wt = (const float4*)(w1 + (size_t)kt * 16 * 256);
#pragma unroll
        for (int i = 0; i < 4; i++) ((float4*)ws)[tid + i * 256] = wt[tid + i * 256];
        __syncthreads();
#pragma unroll
        for (int kk = 0; kk < 16; kk++) {
            float xa0 = xs[r0 * 256 + kt * 16 + kk];
            float xa1 = xs[r1 * 256 + kt * 16 + kk];
            float4 wv0 = *(const float4*)(ws + kk * 256 + lane * 8);
            float4 wv1 = *(const float4*)(ws + kk * 256 + lane * 8 + 4);
            float wb[8] = {wv0.x, wv0.y, wv0.z, wv0.w, wv1.x, wv1.y, wv1.z, wv1.w};
#pragma unroll
            for (int j = 0; j < 8; j++) {
                acc0[j] += xa0 * wb[j];
                acc1[j] += xa1 * wb[j];
            }
        }
    }
    float p0 = 0.f, p1 = 0.f;
#pragma unroll
    for (int j = 0; j < 8; j++) {
        p0 += fmaxf(acc0[j] + b1l[j], 0.f) * w2l[j];
        p1 += fmaxf(acc1[j] + b1l[j], 0.f) * w2l[j];
    }
#pragma unroll
    for (int o = 16; o; o >>= 1) {
        p0 += __shfl_xor_sync(0xffffffffu, p0, o);
        p1 += __shfl_xor_sync(0xffffffffu, p1, o);
    }
    if (lane == 0) {
        float bb = b2[0];
        out[rb + r0] = p0 + bb;
        out[rb + r1] = p1 + bb;
    }
}

// ---------------------------------------------------------------------------
extern "C" void kernel_launch(void* const* d_in, const int* in_sizes, int n_in,
                              void* d_out, int out_size)
{
    const float* beh  = (const float*)d_in[0];
    const float* cand = (const float*)d_in[1];
    const float* fc1w = (const float*)d_in[2];
    const float* fc1b = (const float*)d_in[3];
    const float* fc2w = (const float*)d_in[4];
    // d_in[5] = fc2_b: softmax is shift-invariant, unused.
    const float* m1w  = (const float*)d_in[6];
    const float* m1b  = (const float*)d_in[7];
    const float* m2w  = (const float*)d_in[8];
    const float* m2b  = (const float*)d_in[9];
    float* out = (float*)d_out;

    const int nb = in_sizes[1] / 128;   // batch count (4096)

    int sms = 148;
    cudaDeviceGetAttribute(&sms, cudaDevAttrMultiProcessorCount, 0);

    cudaFuncSetAttribute(din_cand_kernel,
                         cudaFuncAttributeMaxDynamicSharedMemorySize, 98304);
    cudaFuncSetAttribute(din_attn_kernel,
                         cudaFuncAttributeMaxDynamicSharedMemorySize,
                         K1_SMEM_WORDS * 4);

    din_cand_kernel<<<nb / 64, 256, 98304>>>(cand, fc1w, fc1b, nb);
    din_attn_kernel<<<2 * sms, 256, K1_SMEM_WORDS * 4>>>(beh, cand, fc1w, fc2w, nb);
    din_mlp_kernel<<<nb / 16, 256>>>(m1w, m1b, m2w, m2b, out, nb);
}

// round 2
// speedup vs baseline: 1.0484x; 1.0484x over previous
#include <cuda_runtime.h>

// DIN fused kernel set for sm_103a — round 2.
// K0: V = candidate @ W_c + fc1_b            (fp32, 256 CTAs, single wave)
// K1: persistent fused attention per batch   (tf32 mma.sync, cp.async double-buffer,
//                                             N=32/warp register blocking)
// K2: MLP  logit = relu(x@mlp1+b)@mlp2 + b2  (fp32)

#define S_LEN 200
#define E_DIM 128
#define XPAD  132                 // 132 mod 32 == 4 -> conflict-free A-fragment LDS
#define XWORDS (S_LEN * XPAD)     // 26400 floats per X buffer

__device__ float g_V[4096 * 128];   // per-batch candidate projection
__device__ float g_x[4096 * 256];   // concat(user_interest, candidate)

__device__ __forceinline__ float tf32r(float x) {
    unsigned u;
    asm("cvt.rna.tf32.f32 %0, %1;" : "=r"(u) : "f"(x));
    return __uint_as_float(u);
}

__device__ __forceinline__ void mma8(float* d, const float* a, const float* b) {
    asm volatile(
        "mma.sync.aligned.m16n8k8.row.col.f32.tf32.tf32.f32 "
        "{%0,%1,%2,%3}, {%4,%5,%6,%7}, {%8,%9}, {%0,%1,%2,%3};"
        : "+f"(d[0]), "+f"(d[1]), "+f"(d[2]), "+f"(d[3])
        : "r"(__float_as_uint(a[0])), "r"(__float_as_uint(a[1])),
          "r"(__float_as_uint(a[2])), "r"(__float_as_uint(a[3])),
          "r"(__float_as_uint(b[0])), "r"(__float_as_uint(b[1])));
}

// ---------------------------------------------------------------------------
// K0: g_V[b][j] = sum_k cand[b][k] * fc1_w[128+k][j] + fc1_b[j]
// grid = nb/16 = 256 CTAs, 256 threads, 72KB dyn smem, 2 CTAs/SM -> 1 wave.
// Warp w handles rows {2w, 2w+1}; lane owns cols [4*lane, 4*lane+4).
// ---------------------------------------------------------------------------
__global__ __launch_bounds__(256, 2) void din_cand_kernel(
    const float* __restrict__ cand, const float* __restrict__ fc1w,
    const float* __restrict__ fc1b, int nb)
{
    extern __shared__ float s0[];
    float* ws = s0;           // 128 x 128 = 16384
    float* cs = s0 + 16384;   // 16 x 128  = 2048
    const int tid = threadIdx.x;
    const int rowbase = blockIdx.x * 16;

    const float4* w4 = (const float4*)(fc1w + 128 * 128);
#pragma unroll
    for (int i = 0; i < 16; i++) ((float4*)ws)[tid + 256 * i] = w4[tid + 256 * i];
    const float4* c4 = (const float4*)(cand + (size_t)rowbase * 128);
    ((float4*)cs)[tid]       = c4[tid];
    ((float4*)cs)[tid + 256] = c4[tid + 256];
    __syncthreads();

    const int w = tid >> 5, lane = tid & 31;
    const int r0 = 2 * w, r1 = 2 * w + 1;
    float acc0[4] = {0.f, 0.f, 0.f, 0.f};
    float acc1[4] = {0.f, 0.f, 0.f, 0.f};

#pragma unroll 4
    for (int k = 0; k < 128; k++) {
        float x0 = cs[r0 * 128 + k];
        float x1 = cs[r1 * 128 + k];
        float4 wv = *(const float4*)(ws + k * 128 + lane * 4);
        acc0[0] += x0 * wv.x; acc0[1] += x0 * wv.y;
        acc0[2] += x0 * wv.z; acc0[3] += x0 * wv.w;
        acc1[0] += x1 * wv.x; acc1[1] += x1 * wv.y;
        acc1[2] += x1 * wv.z; acc1[3] += x1 * wv.w;
    }
    float4 bb = *(const float4*)(fc1b + lane * 4);
    float4 o0 = make_float4(acc0[0] + bb.x, acc0[1] + bb.y, acc0[2] + bb.z, acc0[3] + bb.w);
    float4 o1 = make_float4(acc1[0] + bb.x, acc1[1] + bb.y, acc1[2] + bb.z, acc1[3] + bb.w);
    *(float4*)(g_V + (size_t)(rowbase + r0) * 128 + lane * 4) = o0;
    *(float4*)(g_V + (size_t)(rowbase + r1) * 128 + lane * 4) = o1;
}

// ---------------------------------------------------------------------------
// K1: persistent fused attention, 1 CTA/SM, 256 threads (8 warps).
// Warp (wc = wid&3, ws = wid>>2): wc owns h-cols [32wc, 32wc+32) (W_b tf32
// B-fragments in 128 regs), ws owns a row half (mt 0..6 / 7..12).
// X double-buffered in smem via cp.async (raw fp32 -> HW tf32 truncation).
// smem: Xs[2][200x132] | part[4][208] | red[64]
// ---------------------------------------------------------------------------
#define K1_SMEM_FLOATS (2 * XWORDS + 4 * 208 + 64)

__global__ __launch_bounds__(256, 1) void din_attn_kernel(
    const float* __restrict__ beh, const float* __restrict__ cand,
    const float* __restrict__ fc1w, const float* __restrict__ fc2w, int nb)
{
    extern __shared__ float sm[];
    float* part = sm + 2 * XWORDS;        // 4 * 208
    float* red  = part + 4 * 208;         // 64

    const int tid = threadIdx.x;
    const int wid = tid >> 5;
    const int lane = tid & 31;
    const int g = lane >> 2;
    const int l4 = lane & 3;
    const int wc = wid & 3;
    const int wrh = wid >> 2;
    const int n0 = wc * 32;

    // ---- preload W_b fragments (tf32-rounded) + w2 (constant across batches) ----
    float Bf[16][4][2];
#pragma unroll
    for (int kt = 0; kt < 16; kt++)
#pragma unroll
        for (int nt = 0; nt < 4; nt++) {
            int n = n0 + nt * 8 + g;
            Bf[kt][nt][0] = tf32r(fc1w[(kt * 8 + l4) * 128 + n]);
            Bf[kt][nt][1] = tf32r(fc1w[(kt * 8 + 4 + l4) * 128 + n]);
        }
    float w2v[4][2];
#pragma unroll
    for (int nt = 0; nt < 4; nt++) {
        int c = n0 + nt * 8 + 2 * l4;
        w2v[nt][0] = fc2w[c];
        w2v[nt][1] = fc2w[c + 1];
    }

    const int stride = gridDim.x;
    const int b0 = blockIdx.x;
    if (b0 >= nb) return;

    // async copy of one batch's X into buffer `buf` (raw fp32, no cvt)
    auto issue_load = [&](int b, int buf) {
        const float4* src = (const float4*)(beh + (size_t)b * (S_LEN * E_DIM));
        unsigned base = (unsigned)__cvta_generic_to_shared(sm + buf * XWORDS);
#pragma unroll
        for (int it = 0; it < 25; it++) {
            int i = tid + it * 256;
            int r = i >> 5, c = i & 31;
            unsigned dst = base + (unsigned)(r * XPAD + c * 4) * 4u;
            asm volatile("cp.async.cg.shared.global [%0], [%1], 16;"
                         :: "r"(dst), "l"(src + i));
        }
    };

    issue_load(b0, 0);
    asm volatile("cp.async.commit_group;");

    int pbuf = 0;
    const int mt_begin = wrh ? 7 : 0;
    const int mt_end   = wrh ? 13 : 7;

    for (int b = b0; b < nb; b += stride) {
        const int nbuf = pbuf ^ 1;
        if (b + stride < nb) issue_load(b + stride, nbuf);
        asm volatile("cp.async.commit_group;");
        asm volatile("cp.async.wait_group 1;");
        __syncthreads();
        float* Xs = sm + pbuf * XWORDS;

        // per-batch candidate projection values for this thread's cols
        float2 vv[4];
#pragma unroll
        for (int nt = 0; nt < 4; nt++)
            vv[nt] = *(const float2*)(g_V + (size_t)b * 128 + n0 + nt * 8 + 2 * l4);

        // ---- mma: h = relu(X@W_b + v), partial score per row ----
        for (int mt = mt_begin; mt < mt_end; mt++) {
            int r0 = mt * 16 + g;
            int r1 = mt * 16 + 8 + g; if (r1 > 199) r1 = 199;  // phantom rows discarded
            const float* x0 = Xs + r0 * XPAD;
            const float* x1 = Xs + r1 * XPAD;
            float acc[4][4];
#pragma unroll
            for (int nt = 0; nt < 4; nt++)
#pragma unroll
                for (int j = 0; j < 4; j++) acc[nt][j] = 0.f;
#pragma unroll
            for (int kt = 0; kt < 16; kt++) {
                float a[4];
                a[0] = x0[kt * 8 + l4];
                a[1] = x1[kt * 8 + l4];
                a[2] = x0[kt * 8 + 4 + l4];
                a[3] = x1[kt * 8 + 4 + l4];
                mma8(acc[0], a, Bf[kt][0]);
                mma8(acc[1], a, Bf[kt][1]);
                mma8(acc[2], a, Bf[kt][2]);
                mma8(acc[3], a, Bf[kt][3]);
            }
            float p0 = 0.f, p1 = 0.f;
#pragma unroll
            for (int nt = 0; nt < 4; nt++) {
                p0 += fmaxf(acc[nt][0] + vv[nt].x, 0.f) * w2v[nt][0]
                    + fmaxf(acc[nt][1] + vv[nt].y, 0.f) * w2v[nt][1];
                p1 += fmaxf(acc[nt][2] + vv[nt].x, 0.f) * w2v[nt][0]
                    + fmaxf(acc[nt][3] + vv[nt].y, 0.f) * w2v[nt][1];
            }
            p0 += __shfl_xor_sync(0xffffffffu, p0, 1);
            p0 += __shfl_xor_sync(0xffffffffu, p0, 2);
            p1 += __shfl_xor_sync(0xffffffffu, p1, 1);
            p1 += __shfl_xor_sync(0xffffffffu, p1, 2);
            if (l4 == 0) {
                part[wc * 208 + mt * 16 + g] = p0;
                part[wc * 208 + mt * 16 + 8 + g] = p1;
            }
        }
        __syncthreads();

        // ---- scores = sum over 4 col-groups (deterministic), softmax ----
        float sc = -3.4e38f;
        if (tid < S_LEN)
            sc = part[tid] + part[208 + tid] + part[416 + tid] + part[624 + tid];
        float mx = sc;
#pragma unroll
        for (int o = 16; o; o >>= 1) mx = fmaxf(mx, __shfl_xor_sync(0xffffffffu, mx, o));
        if (lane == 0) red[wid] = mx;
        __syncthreads();
        mx = red[0];
#pragma unroll
        for (int w = 1; w < 8; w++) mx = fmaxf(mx, red[w]);
        float ex = (tid < S_LEN) ? __expf(sc - mx) : 0.f;
        float sum = ex;
#pragma unroll
        for (int o = 16; o; o >>= 1) sum += __shfl_xor_sync(0xffffffffu, sum, o);
        if (lane == 0) red[8 + wid] = sum;
        __syncthreads();
        sum = 0.f;
#pragma unroll
        for (int w = 0; w < 8; w++) sum += red[8 + w];
        if (tid < S_LEN) part[tid] = ex / sum;   // attn weights
        __syncthreads();

        // ---- user_interest = attn @ X ; write concat(ui, cand) ----
        {
            int e = tid & 127;
            int h = tid >> 7;
            float acc = 0.f;
            int s0i = h * 100;
#pragma unroll 4
            for (int s = s0i; s < s0i + 100; s++)
                acc += part[s] * Xs[s * XPAD + e];
            if (h == 1) {
                part[208 + e] = acc;    // temp (wc=1 partials already consumed)
                g_x[(size_t)b * 256 + 128 + e] = cand[(size_t)b * 128 + e];
            }
            __syncthreads();
            if (h == 0) g_x[(size_t)b * 256 + e] = acc + part[208 + e];
        }
        __syncthreads();   // all smem reads of this batch done before next issue
        pbuf = nbuf;
    }
}

// ---------------------------------------------------------------------------
// K2: logit[r] = relu(x[r]@mlp1 + b1) @ mlp2 + b2
// grid = nb/16, 256 threads; warp ty owns rows {2ty, 2ty+1}, lanes own 8 cols.
// ---------------------------------------------------------------------------
__global__ __launch_bounds__(256) void din_mlp_kernel(
    const float* __restrict__ w1, const float* __restrict__ b1,
    const float* __restrict__ w2, const float* __restrict__ b2,
    float* __restrict__ out, int nb)
{
    __shared__ float xs[16 * 256];
    __shared__ float ws[16 * 256];
    const int tid = threadIdx.x, lane = tid & 31, ty = tid >> 5;
    const int rb = blockIdx.x * 16;

    const float4* x4 = (const float4*)(g_x + (size_t)rb * 256);
#pragma unroll
    for (int i = 0; i < 4; i++) ((float4*)xs)[tid + i * 256] = x4[tid + i * 256];

    float b1l[8], w2l[8];
#pragma unroll
    for (int j = 0; j < 8; j++) {
        b1l[j] = b1[lane * 8 + j];
        w2l[j] = w2[lane * 8 + j];
    }
    float acc0[8], acc1[8];
#pragma unroll
    for (int j = 0; j < 8; j++) { acc0[j] = 0.f; acc1[j] = 0.f; }
    const int r0 = ty * 2, r1 = r0 + 1;

    for (int kt = 0; kt < 16; kt++) {
        __syncthreads();
        const float4* wt = (const float4*)(w1 + (size_t)kt * 16 * 256);
#pragma unroll
        for (int i = 0; i < 4; i++) ((float4*)ws)[tid + i * 256] = wt[tid + i * 256];
        __syncthreads();
#pragma unroll
        for (int kk = 0; kk < 16; kk++) {
            float xa0 = xs[r0 * 256 + kt * 16 + kk];
            float xa1 = xs[r1 * 256 + kt * 16 + kk];
            float4 wv0 = *(const float4*)(ws + kk * 256 + lane * 8);
            float4 wv1 = *(const float4*)(ws + kk * 256 + lane * 8 + 4);
            float wb[8] = {wv0.x, wv0.y, wv0.z, wv0.w, wv1.x, wv1.y, wv1.z, wv1.w};
#pragma unroll
            for (int j = 0; j < 8; j++) {
                acc0[j] += xa0 * wb[j];
                acc1[j] += xa1 * wb[j];
            }
        }
    }
    float p0 = 0.f, p1 = 0.f;
#pragma unroll
    for (int j = 0; j < 8; j++) {
        p0 += fmaxf(acc0[j] + b1l[j], 0.f) * w2l[j];
        p1 += fmaxf(acc1[j] + b1l[j], 0.f) * w2l[j];
    }
#pragma unroll
    for (int o = 16; o; o >>= 1) {
        p0 += __shfl_xor_sync(0xffffffffu, p0, o);
        p1 += __shfl_xor_sync(0xffffffffu, p1, o);
    }
    if (lane == 0) {
        float bb = b2[0];
        out[rb + r0] = p0 + bb;
        out[rb + r1] = p1 + bb;
    }
}

// ---------------------------------------------------------------------------
extern "C" void kernel_launch(void* const* d_in, const int* in_sizes, int n_in,
                              void* d_out, int out_size)
{
    const float* beh  = (const float*)d_in[0];
    const float* cand = (const float*)d_in[1];
    const float* fc1w = (const float*)d_in[2];
    const float* fc1b = (const float*)d_in[3];
    const float* fc2w = (const float*)d_in[4];
    // d_in[5] = fc2_b: softmax is shift-invariant, unused.
    const float* m1w  = (const float*)d_in[6];
    const float* m1b  = (const float*)d_in[7];
    const float* m2w  = (const float*)d_in[8];
    const float* m2b  = (const float*)d_in[9];
    float* out = (float*)d_out;

    const int nb = in_sizes[1] / 128;   // batch count (4096)

    int sms = 148;
    cudaDeviceGetAttribute(&sms, cudaDevAttrMultiProcessorCount, 0);

    cudaFuncSetAttribute(din_cand_kernel,
                         cudaFuncAttributeMaxDynamicSharedMemorySize, 73728);
    cudaFuncSetAttribute(din_attn_kernel,
                         cudaFuncAttributeMaxDynamicSharedMemorySize,
                         K1_SMEM_FLOATS * 4);

    din_cand_kernel<<<nb / 16, 256, 73728>>>(cand, fc1w, fc1b, nb);

    int grid1 = sms < nb ? sms : nb;
    din_attn_kernel<<<grid1, 256, K1_SMEM_FLOATS * 4>>>(beh, cand, fc1w, fc2w, nb);

    din_mlp_kernel<<<nb / 16, 256>>>(m1w, m1b, m2w, m2b, out, nb);
}

// round 4
// speedup vs baseline: 1.2026x; 1.1470x over previous
#include <cuda_runtime.h>
#include <cuda_bf16.h>
#include <cstdint>

// DIN fused kernels for sm_103a (harness compiles at compute_103 -> no tcgen05).
// K1: persistent fused attention: bf16 mma.sync.m16n8k16 + ldmatrix,
//     cp.async staging, candidate projection folded in.
// K2: MLP  logit = relu(x@mlp1+b)@mlp2 + b2  (fp32)

#define S_LEN 200
#define E_DIM 128
#define XSTRB 272            // X bf16 row stride in bytes (136 bf16; 272/16=17 odd -> LDSM conflict-free)

// ---- K1 smem byte offsets ----
#define XBF_OFF   0                       // 208 x 136 bf16 = 56576 B (rows 200-207 zero)
#define STG_OFF   56576                   // 200x128 fp32 cp.async staging = 102400 B
#define WC_OFF    158976                  // 128 x 132 bf16 W_c^T [n][e] = 33792 B
#define VBUF_OFF  192768                  // float[128]  v = cand@W_c + b1
#define PART_OFF  193280                  // float[960]  score partials / attn / temp
#define RED_OFF   197120                  // float[64]
#define CAND_OFF  197376                  // float[128]
#define B1_OFF    197888                  // float[128]
#define SMEM_REQ  198400

__device__ float g_x[4096 * 256];   // concat(user_interest, candidate)

__device__ __forceinline__ uint32_t smem_u32(const void* p) {
    uint32_t a;
    asm("{ .reg .u64 t; cvta.to.shared.u64 t, %1; cvt.u32.u64 %0, t; }"
        : "=r"(a) : "l"(p));
    return a;
}
__device__ __forceinline__ uint32_t packbf(float lo, float hi) {
    uint32_t r;  // first f32 source -> high half
    asm("cvt.rn.bf16x2.f32 %0, %1, %2;" : "=r"(r) : "f"(hi), "f"(lo));
    return r;
}
__device__ __forceinline__ void mma16(float* d, const uint32_t* a, const uint32_t* b) {
    asm volatile(
        "mma.sync.aligned.m16n8k16.row.col.f32.bf16.bf16.f32 "
        "{%0,%1,%2,%3}, {%4,%5,%6,%7}, {%8,%9}, {%0,%1,%2,%3};"
        : "+f"(d[0]), "+f"(d[1]), "+f"(d[2]), "+f"(d[3])
        : "r"(a[0]), "r"(a[1]), "r"(a[2]), "r"(a[3]), "r"(b[0]), "r"(b[1]));
}
__device__ __forceinline__ void ldsm4(uint32_t* r, uint32_t addr) {
    asm volatile("ldmatrix.sync.aligned.m8n8.x4.shared.b16 {%0,%1,%2,%3}, [%4];"
                 : "=r"(r[0]), "=r"(r[1]), "=r"(r[2]), "=r"(r[3]) : "r"(addr));
}

// ---------------------------------------------------------------------------
// K1: persistent fused attention. 256 threads, 8 warps.
// warp: wc = wid&3 owns h-cols [32wc,32wc+32) (W_b bf16 B-frags in 64 regs),
//       wrh = wid>>2 owns row half (mt 0..6 / 7..12).
// ---------------------------------------------------------------------------
__global__ __launch_bounds__(256, 1) void din_attn_kernel(
    const float* __restrict__ beh, const float* __restrict__ cand,
    const float* __restrict__ fc1w, const float* __restrict__ fc1b,
    const float* __restrict__ fc2w, int nb)
{
    extern __shared__ __align__(16) char Ab[];
    const uint32_t A = smem_u32(Ab);

    float* stgF  = (float*)(Ab + STG_OFF);
    float* vbuf  = (float*)(Ab + VBUF_OFF);
    float* part  = (float*)(Ab + PART_OFF);
    float* red   = (float*)(Ab + RED_OFF);
    float* cands = (float*)(Ab + CAND_OFF);
    float* b1s   = (float*)(Ab + B1_OFF);

    const int tid = threadIdx.x, wid = tid >> 5, lane = tid & 31;
    const int g = lane >> 2, t4 = lane & 3;
    const int wc = wid & 3, wrh = wid >> 2;
    const int n0 = wc * 32;
    const int stride = gridDim.x;
    const int b0 = blockIdx.x;
    if (b0 >= nb) return;

    // ================= one-time init =================
    // W_b fp32 -> staging smem (coalesced)
    {
        const float4* w4 = (const float4*)fc1w;
        float4* s4 = (float4*)stgF;
#pragma unroll
        for (int i = 0; i < 16; i++) s4[tid + i * 256] = w4[tid + i * 256];
    }
    // W_c -> bf16 smem [n][e], stride 132
    for (int idx = tid; idx < 128 * 128; idx += 256) {
        int e = idx >> 7, n = idx & 127;
        *(__nv_bfloat16*)(Ab + WC_OFF + (uint32_t)(n * 132 + e) * 2) =
            __float2bfloat16_rn(fc1w[128 * 128 + idx]);
    }
    if (tid < 128) { b1s[tid] = fc1b[tid]; vbuf[tid] = fc2w[tid]; }
    // zero phantom X rows 200..207
    for (int i = tid; i < 1088; i += 256)
        *(uint16_t*)(Ab + XBF_OFF + 200 * XSTRB + i * 2) = 0;
    __syncthreads();

    // gather W_b B-fragments from staging: Bf[kt][nt] = {b0,b1}
    uint32_t Bf[8][4][2];
#pragma unroll
    for (int kt = 0; kt < 8; kt++)
#pragma unroll
        for (int nt = 0; nt < 4; nt++) {
            int n = n0 + nt * 8 + g;
            int r = kt * 16 + 2 * t4;
            Bf[kt][nt][0] = packbf(stgF[r * 128 + n],       stgF[(r + 1) * 128 + n]);
            Bf[kt][nt][1] = packbf(stgF[(r + 8) * 128 + n], stgF[(r + 9) * 128 + n]);
        }
    float w2v[4][2];
#pragma unroll
    for (int nt = 0; nt < 4; nt++) {
        w2v[nt][0] = vbuf[n0 + nt * 8 + 2 * t4];
        w2v[nt][1] = vbuf[n0 + nt * 8 + 2 * t4 + 1];
    }
    __syncthreads();   // staging free for cp.async

    // cp.async batch b -> staging
    auto issue_load = [&](int b) {
        const float4* src = (const float4*)(beh + (size_t)b * (S_LEN * E_DIM));
        uint32_t dst = A + STG_OFF + (uint32_t)tid * 16u;
#pragma unroll
        for (int it = 0; it < 25; it++)
            asm volatile("cp.async.cg.shared.global [%0], [%1], 16;"
                         :: "r"(dst + it * 4096u), "l"(src + tid + it * 256) : "memory");
    };
    issue_load(b0);
    asm volatile("cp.async.commit_group;" ::: "memory");

    // ldmatrix base address for this lane (within a 16-row tile)
    const uint32_t lm_base = A + XBF_OFF + (uint32_t)(lane & 15) * XSTRB
                           + ((lane & 16) ? 16u : 0u);
    const int mt_begin = wrh ? 7 : 0;
    const int mt_end   = wrh ? 13 : 7;

    for (int b = b0; b < nb; b += stride) {
        // candidate prefetch (regs)
        float4 cv;
        if (tid < 32) cv = ((const float4*)(cand + (size_t)b * 128))[tid];

        asm volatile("cp.async.wait_group 0;" ::: "memory");
        __syncthreads();

        // ---- convert staging fp32 -> Xbf bf16 ----
#pragma unroll
        for (int it = 0; it < 25; it++) {
            int i = tid + it * 256;
            float4 v = ((const float4*)stgF)[i];
            int s = i >> 5, e0 = (i & 31) * 4;
            uint2 pk = make_uint2(packbf(v.x, v.y), packbf(v.z, v.w));
            *(uint2*)(Ab + XBF_OFF + (uint32_t)s * XSTRB + (uint32_t)e0 * 2) = pk;
        }
        if (tid < 32) ((float4*)cands)[tid] = cv;
        __syncthreads();   // staging consumed, Xbf + cands ready

        if (b + stride < nb) issue_load(b + stride);
        asm volatile("cp.async.commit_group;" ::: "memory");

        // ---- v = cand @ W_c + b1 ----
        {
            int n = tid >> 1, h2 = tid & 1;
            const uint32_t* wrow = (const uint32_t*)(Ab + WC_OFF) + n * 66 + h2 * 32;
            const float2* cd = (const float2*)cands + h2 * 32;
            float a = 0.f;
#pragma unroll 8
            for (int k = 0; k < 32; k++) {
                uint32_t wv = wrow[k];
                __nv_bfloat162 p = *reinterpret_cast<__nv_bfloat162*>(&wv);
                float2 c = cd[k];
                a += c.x * __bfloat162float(p.x) + c.y * __bfloat162float(p.y);
            }
            a += __shfl_xor_sync(0xffffffffu, a, 1);
            if (h2 == 0) vbuf[n] = a + b1s[n];
            if (tid < 128) g_x[(size_t)b * 256 + 128 + tid] = cands[tid];
        }
        __syncthreads();   // vbuf visible

        float2 vv[4];
#pragma unroll
        for (int nt = 0; nt < 4; nt++)
            vv[nt] = *(const float2*)(vbuf + n0 + nt * 8 + 2 * t4);

        // ---- mma: h = relu(X@W_b + v); per-row score partials ----
        for (int mt = mt_begin; mt < mt_end; mt++) {
            uint32_t abase = lm_base + (uint32_t)mt * 16u * XSTRB;
            float acc[4][4];
#pragma unroll
            for (int nt = 0; nt < 4; nt++)
#pragma unroll
                for (int j = 0; j < 4; j++) acc[nt][j] = 0.f;
#pragma unroll
            for (int kt = 0; kt < 8; kt++) {
                uint32_t a[4];
                ldsm4(a, abase + (uint32_t)kt * 32u);
                mma16(acc[0], a, Bf[kt][0]);
                mma16(acc[1], a, Bf[kt][1]);
                mma16(acc[2], a, Bf[kt][2]);
                mma16(acc[3], a, Bf[kt][3]);
            }
            float p0 = 0.f, p1 = 0.f;
#pragma unroll
            for (int nt = 0; nt < 4; nt++) {
                p0 += fmaxf(acc[nt][0] + vv[nt].x, 0.f) * w2v[nt][0]
                    + fmaxf(acc[nt][1] + vv[nt].y, 0.f) * w2v[nt][1];
                p1 += fmaxf(acc[nt][2] + vv[nt].x, 0.f) * w2v[nt][0]
                    + fmaxf(acc[nt][3] + vv[nt].y, 0.f) * w2v[nt][1];
            }
            p0 += __shfl_xor_sync(0xffffffffu, p0, 1);
            p0 += __shfl_xor_sync(0xffffffffu, p0, 2);
            p1 += __shfl_xor_sync(0xffffffffu, p1, 1);
            p1 += __shfl_xor_sync(0xffffffffu, p1, 2);
            if (t4 == 0) {
                int r_lo = mt * 16 + g, r_hi = mt * 16 + 8 + g;
                part[wc * 208 + r_lo] = p0;
                if (r_hi < S_LEN) part[wc * 208 + r_hi] = p1;
            }
        }
        __syncthreads();

        // ---- softmax over 200 scores ----
        float sc = -3.4e38f;
        if (tid < S_LEN)
            sc = part[tid] + part[208 + tid] + part[416 + tid] + part[624 + tid];
        float mx = sc;
#pragma unroll
        for (int o = 16; o; o >>= 1) mx = fmaxf(mx, __shfl_xor_sync(0xffffffffu, mx, o));
        if (lane == 0) red[wid] = mx;
        __syncthreads();
        mx = red[0];
#pragma unroll
        for (int w = 1; w < 8; w++) mx = fmaxf(mx, red[w]);
        float ex = (tid < S_LEN) ? __expf(sc - mx) : 0.f;
        float sum = ex;
#pragma unroll
        for (int o = 16; o; o >>= 1) sum += __shfl_xor_sync(0xffffffffu, sum, o);
        if (lane == 0) red[8 + wid] = sum;
        __syncthreads();
        sum = 0.f;
#pragma unroll
        for (int w = 0; w < 8; w++) sum += red[8 + w];
        if (tid < S_LEN) part[tid] = ex / sum;   // attn weights
        __syncthreads();

        // ---- user_interest = attn @ X (bf16) ----
        {
            int e = tid & 127, h = tid >> 7;
            float acc = 0.f;
            int s0 = h * 100;
#pragma unroll 4
            for (int s = s0; s < s0 + 100; s++)
                acc += part[s] * __bfloat162float(
                    *(const __nv_bfloat16*)(Ab + XBF_OFF + (uint32_t)s * XSTRB + (uint32_t)e * 2));
            if (h == 1) part[832 + e] = acc;
            __syncthreads();
            if (h == 0) g_x[(size_t)b * 256 + e] = acc + part[832 + e];
        }
    }
}

// ---------------------------------------------------------------------------
// K2: logit[r] = relu(x[r]@mlp1 + b1) @ mlp2 + b2
// ---------------------------------------------------------------------------
__global__ __launch_bounds__(256) void din_mlp_kernel(
    const float* __restrict__ w1, const float* __restrict__ b1,
    const float* __restrict__ w2, const float* __restrict__ b2,
    float* __restrict__ out, int nb)
{
    __shared__ float xs[16 * 256];
    __shared__ float ws[16 * 256];
    const int tid = threadIdx.x, lane = tid & 31, ty = tid >> 5;
    const int rb = blockIdx.x * 16;

    const float4* x4 = (const float4*)(g_x + (size_t)rb * 256);
#pragma unroll
    for (int i = 0; i < 4; i++) ((float4*)xs)[tid + i * 256] = x4[tid + i * 256];

    float b1l[8], w2l[8];
#pragma unroll
    for (int j = 0; j < 8; j++) {
        b1l[j] = b1[lane * 8 + j];
        w2l[j] = w2[lane * 8 + j];
    }
    float acc0[8], acc1[8];
#pragma unroll
    for (int j = 0; j < 8; j++) { acc0[j] = 0.f; acc1[j] = 0.f; }
    const int r0 = ty * 2, r1 = r0 + 1;

    for (int kt = 0; kt < 16; kt++) {
        __syncthreads();
        const float4* wt = (const float4*)(w1 + (size_t)kt * 16 * 256);
#pragma unroll
        for (int i = 0; i < 4; i++) ((float4*)ws)[tid + i * 256] = wt[tid + i * 256];
        __syncthreads();
#pragma unroll
        for (int kk = 0; kk < 16; kk++) {
            float xa0 = xs[r0 * 256 + kt * 16 + kk];
            float xa1 = xs[r1 * 256 + kt * 16 + kk];
            float4 wv0 = *(const float4*)(ws + kk * 256 + lane * 8);
            float4 wv1 = *(const float4*)(ws + kk * 256 + lane * 8 + 4);
            float wb[8] = {wv0.x, wv0.y, wv0.z, wv0.w, wv1.x, wv1.y, wv1.z, wv1.w};
#pragma unroll
            for (int j = 0; j < 8; j++) {
                acc0[j] += xa0 * wb[j];
                acc1[j] += xa1 * wb[j];
            }
        }
    }
    float p0 = 0.f, p1 = 0.f;
#pragma unroll
    for (int j = 0; j < 8; j++) {
        p0 += fmaxf(acc0[j] + b1l[j], 0.f) * w2l[j];
        p1 += fmaxf(acc1[j] + b1l[j], 0.f) * w2l[j];
    }
#pragma unroll
    for (int o = 16; o; o >>= 1) {
        p0 += __shfl_xor_sync(0xffffffffu, p0, o);
        p1 += __shfl_xor_sync(0xffffffffu, p1, o);
    }
    if (lane == 0) {
        float bb = b2[0];
        out[rb + r0] = p0 + bb;
        out[rb + r1] = p1 + bb;
    }
}

// ---------------------------------------------------------------------------
extern "C" void kernel_launch(void* const* d_in, const int* in_sizes, int n_in,
                              void* d_out, int out_size)
{
    const float* beh  = (const float*)d_in[0];
    const float* cand = (const float*)d_in[1];
    const float* fc1w = (const float*)d_in[2];
    const float* fc1b = (const float*)d_in[3];
    const float* fc2w = (const float*)d_in[4];
    // d_in[5] = fc2_b: softmax shift-invariant, unused.
    const float* m1w  = (const float*)d_in[6];
    const float* m1b  = (const float*)d_in[7];
    const float* m2w  = (const float*)d_in[8];
    const float* m2b  = (const float*)d_in[9];
    float* out = (float*)d_out;

    const int nb = in_sizes[1] / 128;   // 4096

    int sms = 148;
    cudaDeviceGetAttribute(&sms, cudaDevAttrMultiProcessorCount, 0);

    cudaFuncSetAttribute(din_attn_kernel,
                         cudaFuncAttributeMaxDynamicSharedMemorySize, SMEM_REQ);

    int grid1 = sms < nb ? sms : nb;
    din_attn_kernel<<<grid1, 256, SMEM_REQ>>>(beh, cand, fc1w, fc1b, fc2w, nb);

    din_mlp_kernel<<<nb / 16, 256>>>(m1w, m1b, m2w, m2b, out, nb);
}

// round 5
// speedup vs baseline: 1.4717x; 1.2238x over previous
#include <cuda_runtime.h>
#include <cuda_bf16.h>
#include <cstdint>

// DIN fused kernels for sm_103a — round 5.
// K1: persistent fused attention (bf16 mma.sync + ldmatrix), no staging buffer,
//     direct LDG->cvt->STS, 2 CTAs/SM. Candidate projection folded in.
// K2: MLP, 32 rows/CTA, warp-row/lane-col layout, cp.async double-buffered w1.

#define S_LEN 200
#define E_DIM 128
#define XSTRB 272            // X bf16 row stride bytes (136 bf16, odd 16B units -> LDSM conflict-free)

// ---- K1 smem byte offsets (total 96000 B -> 2 CTAs/SM) ----
#define XBF_OFF   0                       // 208 x 136 bf16 = 56576 (rows 200-207 zero)
#define WC_OFF    56576                   // 128 x 132 bf16 W_c^T [n][e] = 33792
#define VBUF_OFF  90368                   // float[128]
#define PART_OFF  90880                   // float[960]
#define RED_OFF   94720                   // float[64]
#define CAND_OFF  94976                   // float[128]
#define B1_OFF    95488                   // float[128]
#define SMEM_REQ  96000

__device__ float g_ui[4096 * 128];   // user_interest

__device__ __forceinline__ uint32_t smem_u32(const void* p) {
    uint32_t a;
    asm("{ .reg .u64 t; cvta.to.shared.u64 t, %1; cvt.u32.u64 %0, t; }"
        : "=r"(a) : "l"(p));
    return a;
}
__device__ __forceinline__ uint32_t packbf(float lo, float hi) {
    uint32_t r;  // first f32 source -> high half
    asm("cvt.rn.bf16x2.f32 %0, %1, %2;" : "=r"(r) : "f"(hi), "f"(lo));
    return r;
}
__device__ __forceinline__ void mma16(float* d, const uint32_t* a, const uint32_t* b) {
    asm volatile(
        "mma.sync.aligned.m16n8k16.row.col.f32.bf16.bf16.f32 "
        "{%0,%1,%2,%3}, {%4,%5,%6,%7}, {%8,%9}, {%0,%1,%2,%3};"
        : "+f"(d[0]), "+f"(d[1]), "+f"(d[2]), "+f"(d[3])
        : "r"(a[0]), "r"(a[1]), "r"(a[2]), "r"(a[3]), "r"(b[0]), "r"(b[1]));
}
__device__ __forceinline__ void ldsm4(uint32_t* r, uint32_t addr) {
    asm volatile("ldmatrix.sync.aligned.m8n8.x4.shared.b16 {%0,%1,%2,%3}, [%4];"
                 : "=r"(r[0]), "=r"(r[1]), "=r"(r[2]), "=r"(r[3]) : "r"(addr));
}

// ---------------------------------------------------------------------------
// K1: persistent fused attention. 256 threads, 8 warps, 2 CTAs/SM.
// wc = wid&3 owns h-cols [32wc,32wc+32) (W_b B-frags in 64 regs),
// wrh = wid>>2 owns row half (mt 0..6 / 7..12).
// ---------------------------------------------------------------------------
__global__ __launch_bounds__(256, 2) void din_attn_kernel(
    const float* __restrict__ beh, const float* __restrict__ cand,
    const float* __restrict__ fc1w, const float* __restrict__ fc1b,
    const float* __restrict__ fc2w, int nb)
{
    extern __shared__ __align__(16) char Ab[];
    const uint32_t A = smem_u32(Ab);

    float* vbuf  = (float*)(Ab + VBUF_OFF);
    float* part  = (float*)(Ab + PART_OFF);
    float* red   = (float*)(Ab + RED_OFF);
    float* cands = (float*)(Ab + CAND_OFF);
    float* b1s   = (float*)(Ab + B1_OFF);

    const int tid = threadIdx.x, wid = tid >> 5, lane = tid & 31;
    const int g = lane >> 2, t4 = lane & 3;
    const int wc = wid & 3, wrh = wid >> 2;
    const int n0 = wc * 32;
    const int stride = gridDim.x;
    const int b0 = blockIdx.x;
    if (b0 >= nb) return;

    // ================= one-time init =================
    // stage W_b fp32 into smem base (64KB scratch over XBF/WC region)
    {
        const float4* w4 = (const float4*)fc1w;
        float4* s4 = (float4*)Ab;
#pragma unroll
        for (int i = 0; i < 16; i++) s4[tid + i * 256] = w4[tid + i * 256];
    }
    __syncthreads();
    // gather W_b B-fragments
    uint32_t Bf[8][4][2];
    {
        const float* stgF = (const float*)Ab;
#pragma unroll
        for (int kt = 0; kt < 8; kt++)
#pragma unroll
            for (int nt = 0; nt < 4; nt++) {
                int n = n0 + nt * 8 + g;
                int r = kt * 16 + 2 * t4;
                Bf[kt][nt][0] = packbf(stgF[r * 128 + n],       stgF[(r + 1) * 128 + n]);
                Bf[kt][nt][1] = packbf(stgF[(r + 8) * 128 + n], stgF[(r + 9) * 128 + n]);
            }
    }
    float w2v[4][2];
#pragma unroll
    for (int nt = 0; nt < 4; nt++) {
        w2v[nt][0] = fc2w[n0 + nt * 8 + 2 * t4];
        w2v[nt][1] = fc2w[n0 + nt * 8 + 2 * t4 + 1];
    }
    __syncthreads();   // staging consumed

    // W_c -> bf16 smem [n][e] stride 132; b1; zero phantom X rows
    for (int idx = tid; idx < 128 * 128; idx += 256) {
        int e = idx >> 7, n = idx & 127;
        *(__nv_bfloat16*)(Ab + WC_OFF + (uint32_t)(n * 132 + e) * 2) =
            __float2bfloat16_rn(fc1w[128 * 128 + idx]);
    }
    if (tid < 128) b1s[tid] = fc1b[tid];
    for (int i = tid; i < 1088; i += 256)
        *(uint16_t*)(Ab + XBF_OFF + 200 * XSTRB + i * 2) = 0;

    const uint32_t lm_base = A + XBF_OFF + (uint32_t)(lane & 15) * XSTRB
                           + ((lane & 16) ? 16u : 0u);
    const int mt_begin = wrh ? 7 : 0;
    const int mt_end   = wrh ? 13 : 7;

    for (int b = b0; b < nb; b += stride) {
        __syncthreads();   // previous batch's XBF readers done

        // ---- X: LDG fp32 -> cvt -> STS bf16 ----
        const float4* src = (const float4*)(beh + (size_t)b * (S_LEN * E_DIM));
#pragma unroll
        for (int it = 0; it < 25; it++) {
            int i = tid + it * 256;
            float4 v = src[i];
            int s = i >> 5, e0 = (i & 31) * 4;
            uint2 pk = make_uint2(packbf(v.x, v.y), packbf(v.z, v.w));
            *(uint2*)(Ab + XBF_OFF + (uint32_t)s * XSTRB + (uint32_t)e0 * 2) = pk;
        }
        if (tid < 32)
            ((float4*)cands)[tid] = ((const float4*)(cand + (size_t)b * 128))[tid];
        __syncthreads();   // XBF + cands ready

        // ---- v = cand @ W_c + b1 ----
        {
            int n = tid >> 1, h2 = tid & 1;
            const uint32_t* wrow = (const uint32_t*)(Ab + WC_OFF) + n * 66 + h2 * 32;
            const float2* cd = (const float2*)cands + h2 * 32;
            float a = 0.f;
#pragma unroll 8
            for (int k = 0; k < 32; k++) {
                uint32_t wv = wrow[k];
                __nv_bfloat162 p = *reinterpret_cast<__nv_bfloat162*>(&wv);
                float2 c = cd[k];
                a += c.x * __bfloat162float(p.x) + c.y * __bfloat162float(p.y);
            }
            a += __shfl_xor_sync(0xffffffffu, a, 1);
            if (h2 == 0) vbuf[n] = a + b1s[n];
        }
        __syncthreads();   // vbuf visible

        float2 vv[4];
#pragma unroll
        for (int nt = 0; nt < 4; nt++)
            vv[nt] = *(const float2*)(vbuf + n0 + nt * 8 + 2 * t4);

        // ---- mma: h = relu(X@W_b + v); per-row score partials ----
        for (int mt = mt_begin; mt < mt_end; mt++) {
            uint32_t abase = lm_base + (uint32_t)mt * 16u * XSTRB;
            float acc[4][4];
#pragma unroll
            for (int nt = 0; nt < 4; nt++)
#pragma unroll
                for (int j = 0; j < 4; j++) acc[nt][j] = 0.f;
#pragma unroll
            for (int kt = 0; kt < 8; kt++) {
                uint32_t a[4];
                ldsm4(a, abase + (uint32_t)kt * 32u);
                mma16(acc[0], a, Bf[kt][0]);
                mma16(acc[1], a, Bf[kt][1]);
                mma16(acc[2], a, Bf[kt][2]);
                mma16(acc[3], a, Bf[kt][3]);
            }
            float p0 = 0.f, p1 = 0.f;
#pragma unroll
            for (int nt = 0; nt < 4; nt++) {
                p0 += fmaxf(acc[nt][0] + vv[nt].x, 0.f) * w2v[nt][0]
                    + fmaxf(acc[nt][1] + vv[nt].y, 0.f) * w2v[nt][1];
                p1 += fmaxf(acc[nt][2] + vv[nt].x, 0.f) * w2v[nt][0]
                    + fmaxf(acc[nt][3] + vv[nt].y, 0.f) * w2v[nt][1];
            }
            p0 += __shfl_xor_sync(0xffffffffu, p0, 1);
            p0 += __shfl_xor_sync(0xffffffffu, p0, 2);
            p1 += __shfl_xor_sync(0xffffffffu, p1, 1);
            p1 += __shfl_xor_sync(0xffffffffu, p1, 2);
            if (t4 == 0) {
                int r_lo = mt * 16 + g, r_hi = mt * 16 + 8 + g;
                part[wc * 208 + r_lo] = p0;
                if (r_hi < S_LEN) part[wc * 208 + r_hi] = p1;
            }
        }
        __syncthreads();

        // ---- softmax over 200 scores ----
        float sc = -3.4e38f;
        if (tid < S_LEN)
            sc = part[tid] + part[208 + tid] + part[416 + tid] + part[624 + tid];
        float mx = sc;
#pragma unroll
        for (int o = 16; o; o >>= 1) mx = fmaxf(mx, __shfl_xor_sync(0xffffffffu, mx, o));
        if (lane == 0) red[wid] = mx;
        __syncthreads();
        mx = red[0];
#pragma unroll
        for (int w = 1; w < 8; w++) mx = fmaxf(mx, red[w]);
        float ex = (tid < S_LEN) ? __expf(sc - mx) : 0.f;
        float sum = ex;
#pragma unroll
        for (int o = 16; o; o >>= 1) sum += __shfl_xor_sync(0xffffffffu, sum, o);
        if (lane == 0) red[8 + wid] = sum;
        __syncthreads();
        sum = 0.f;
#pragma unroll
        for (int w = 0; w < 8; w++) sum += red[8 + w];
        if (tid < S_LEN) part[tid] = ex / sum;   // attn weights
        __syncthreads();

        // ---- user_interest = attn @ X (bf16) ----
        {
            int e = tid & 127, h = tid >> 7;
            float acc = 0.f;
            int s0 = h * 100;
#pragma unroll 4
            for (int s = s0; s < s0 + 100; s++)
                acc += part[s] * __bfloat162float(
                    *(const __nv_bfloat16*)(Ab + XBF_OFF + (uint32_t)s * XSTRB + (uint32_t)e * 2));
            if (h == 1) part[832 + e] = acc;
            __syncthreads();
            if (h == 0) g_ui[(size_t)b * 128 + e] = acc + part[832 + e];
        }
    }
}

// ---------------------------------------------------------------------------
// K2: logit[r] = relu([ui|cand]@mlp1 + b1) @ mlp2 + b2
// grid = nb/32, 256 threads. Warp w owns rows 4w..4w+3 (x via LDS broadcast),
// lane owns 8 cols. w1 streamed in 16-row tiles, cp.async double-buffered.
// ---------------------------------------------------------------------------
#define K2_SMEM (32 * 256 * 4 + 2 * 16 * 256 * 4)   // 65536

__global__ __launch_bounds__(256, 1) void din_mlp_kernel(
    const float* __restrict__ cand,
    const float* __restrict__ w1, const float* __restrict__ b1,
    const float* __restrict__ w2, const float* __restrict__ b2,
    float* __restrict__ out, int nb)
{
    extern __shared__ __align__(16) float s2[];
    float* xs = s2;              // 32 x 256
    float* ws = s2 + 8192;       // 2 x 16 x 256
    const uint32_t wsA = smem_u32(ws);

    const int tid = threadIdx.x, lane = tid & 31, w = tid >> 5;
    const int rb = blockIdx.x * 32;

    // xs rows = [g_ui | cand]
#pragma unroll
    for (int i = 0; i < 4; i++) {
        int idx = tid + i * 256;           // 0..1023 (32 rows x 32 f4)
        int r = idx >> 5, c4 = idx & 31;
        ((float4*)xs)[r * 64 + c4]      = ((const float4*)(g_ui + (size_t)(rb + r) * 128))[c4];
        ((float4*)xs)[r * 64 + 32 + c4] = ((const float4*)(cand + (size_t)(rb + r) * 128))[c4];
    }

    auto issue = [&](int kt, int buf) {
        const float4* src = (const float4*)(w1 + (size_t)kt * 4096);
        uint32_t dst = wsA + (uint32_t)buf * 16384u + (uint32_t)tid * 16u;
#pragma unroll
        for (int i = 0; i < 4; i++)
            asm volatile("cp.async.cg.shared.global [%0], [%1], 16;"
                         :: "r"(dst + i * 4096u), "l"(src + tid + i * 256) : "memory");
    };
    issue(0, 0);
    asm volatile("cp.async.commit_group;" ::: "memory");

    float b1l[8], w2l[8];
#pragma unroll
    for (int j = 0; j < 8; j++) {
        b1l[j] = b1[lane * 8 + j];
        w2l[j] = w2[lane * 8 + j];
    }

    float acc[4][8];
#pragma unroll
    for (int i = 0; i < 4; i++)
#pragma unroll
        for (int j = 0; j < 8; j++) acc[i][j] = 0.f;

    for (int kt = 0; kt < 16; kt++) {
        asm volatile("cp.async.wait_group 0;" ::: "memory");
        __syncthreads();
        if (kt < 15) {
            issue(kt + 1, (kt + 1) & 1);
            asm volatile("cp.async.commit_group;" ::: "memory");
        }
        const float* wt = ws + (kt & 1) * 4096;
#pragma unroll
        for (int kk = 0; kk < 16; kk++) {
            int k = kt * 16 + kk;
            float x0 = xs[(4 * w + 0) * 256 + k];
            float x1 = xs[(4 * w + 1) * 256 + k];
            float x2 = xs[(4 * w + 2) * 256 + k];
            float x3 = xs[(4 * w + 3) * 256 + k];
            float4 a4 = *(const float4*)(wt + kk * 256 + lane * 8);
            float4 c4 = *(const float4*)(wt + kk * 256 + lane * 8 + 4);
            float wb[8] = {a4.x, a4.y, a4.z, a4.w, c4.x, c4.y, c4.z, c4.w};
#pragma unroll
            for (int j = 0; j < 8; j++) {
                acc[0][j] += x0 * wb[j];
                acc[1][j] += x1 * wb[j];
                acc[2][j] += x2 * wb[j];
                acc[3][j] += x3 * wb[j];
            }
        }
    }

    // epilogue: relu + dot(w2), per-row lane reduction
    float p[4];
#pragma unroll
    for (int i = 0; i < 4; i++) {
        float s = 0.f;
#pragma unroll
        for (int j = 0; j < 8; j++)
            s += fmaxf(acc[i][j] + b1l[j], 0.f) * w2l[j];
        p[i] = s;
    }
#pragma unroll
    for (int o = 16; o; o >>= 1) {
#pragma unroll
        for (int i = 0; i < 4; i++)
            p[i] += __shfl_xor_sync(0xffffffffu, p[i], o);
    }
    if (lane == 0) {
        float bb = b2[0];
#pragma unroll
        for (int i = 0; i < 4; i++)
            out[rb + 4 * w + i] = p[i] + bb;
    }
}

// ---------------------------------------------------------------------------
extern "C" void kernel_launch(void* const* d_in, const int* in_sizes, int n_in,
                              void* d_out, int out_size)
{
    const float* beh  = (const float*)d_in[0];
    const float* cand = (const float*)d_in[1];
    const float* fc1w = (const float*)d_in[2];
    const float* fc1b = (const float*)d_in[3];
    const float* fc2w = (const float*)d_in[4];
    // d_in[5] = fc2_b: softmax shift-invariant, unused.
    const float* m1w  = (const float*)d_in[6];
    const float* m1b  = (const float*)d_in[7];
    const float* m2w  = (const float*)d_in[8];
    const float* m2b  = (const float*)d_in[9];
    float* out = (float*)d_out;

    const int nb = in_sizes[1] / 128;   // 4096

    int sms = 148;
    cudaDeviceGetAttribute(&sms, cudaDevAttrMultiProcessorCount, 0);

    cudaFuncSetAttribute(din_attn_kernel,
                         cudaFuncAttributeMaxDynamicSharedMemorySize, SMEM_REQ);
    cudaFuncSetAttribute(din_mlp_kernel,
                         cudaFuncAttributeMaxDynamicSharedMemorySize, K2_SMEM);

    int grid1 = 2 * sms;
    if (grid1 > nb) grid1 = nb;
    din_attn_kernel<<<grid1, 256, SMEM_REQ>>>(beh, cand, fc1w, fc1b, fc2w, nb);

    din_mlp_kernel<<<nb / 32, 256, K2_SMEM>>>(cand, m1w, m1b, m2w, m2b, out, nb);
}